// round 1
// baseline (speedup 1.0000x reference)
#include <cuda_runtime.h>
#include <math.h>

#define NN 256
#define HH 256
#define DDE 64
#define NHD 4
#define CHUNK 64

// ---------------- device scratch (static, no allocations) ----------------
__device__ float g_tT[HH * NN];    // tT[h*N + j] = tanh(ahs[j,h])
__device__ float g_PT[DDE * NN];   // PT[d*N + j] = action[j],goal[j] part of dist@W_dist
__device__ float g_C [NN * DDE];   // C[i*DDE + d] = action[i],goal[i] part + b_dist
__device__ float g_u [NHD * HH];   // u[z*H+h] = sum_f wm[z,h,f]*a[f]
__device__ float g_v [NHD * HH];   // v[z*H+h] = sum_f wm[z,h,f]*a[H+f]
__device__ float g_c1[NHD * NN];   // c1[z*N+n] = ahs[n]·u[z]
__device__ float g_s0[NHD * NN];   // s0[z*N+n] = ahs[n]·v[z]

// ---------------- prep kernels ----------------
__global__ void prepA(const float* __restrict__ ahs, const float* __restrict__ goal,
                      const float* __restrict__ action, const float* __restrict__ Wd,
                      const float* __restrict__ bd) {
    const int j = blockIdx.x, t = threadIdx.x;
    g_tT[t * NN + j] = tanhf(ahs[j * HH + t]);
    if (t < DDE) {
        const float a0 = action[j * 2 + 0], a1 = action[j * 2 + 1];
        const float go0 = goal[j * 2 + 0], go1 = goal[j * 2 + 1];
        g_PT[t * NN + j] = a0 * Wd[4 * DDE + t] + a1 * Wd[5 * DDE + t]
                         + go0 * Wd[6 * DDE + t] + go1 * Wd[7 * DDE + t];
        g_C[j * DDE + t] = a0 * Wd[0 * DDE + t] + a1 * Wd[1 * DDE + t]
                         + go0 * Wd[2 * DDE + t] + go1 * Wd[3 * DDE + t] + bd[t];
    }
}

// u[z,h], v[z,h]: one warp per (z,h) row of wm
__global__ void prepB(const float* __restrict__ w, const float* __restrict__ a) {
    const int warp = (blockIdx.x * blockDim.x + threadIdx.x) >> 5;  // 0..1023 = z*256+h
    const int lane = threadIdx.x & 31;
    const float* row = w + warp * HH;
    float su = 0.f, sv = 0.f;
    #pragma unroll
    for (int f = lane; f < HH; f += 32) {
        const float wv = row[f];
        su = fmaf(wv, a[f], su);
        sv = fmaf(wv, a[HH + f], sv);
    }
    #pragma unroll
    for (int o = 16; o; o >>= 1) {
        su += __shfl_down_sync(0xffffffffu, su, o);
        sv += __shfl_down_sync(0xffffffffu, sv, o);
    }
    if (lane == 0) { g_u[warp] = su; g_v[warp] = sv; }
}

// c1[z,n], s0[z,n]: one warp per (z,n)
__global__ void prepC(const float* __restrict__ ahs) {
    const int warp = (blockIdx.x * blockDim.x + threadIdx.x) >> 5;  // 0..1023 = z*256+n
    const int lane = threadIdx.x & 31;
    const int z = warp >> 8, n = warp & 255;
    float sc = 0.f, ss = 0.f;
    #pragma unroll
    for (int h = lane; h < HH; h += 32) {
        const float av = ahs[n * HH + h];
        sc = fmaf(av, g_u[z * HH + h], sc);
        ss = fmaf(av, g_v[z * HH + h], ss);
    }
    #pragma unroll
    for (int o = 16; o; o >>= 1) {
        sc += __shfl_down_sync(0xffffffffu, sc, o);
        ss += __shfl_down_sync(0xffffffffu, ss, o);
    }
    if (lane == 0) { g_c1[warp] = sc; g_s0[warp] = ss; }
}

// ---------------- main fused kernel: one block per row i ----------------
// shared layout (floats):
//   Wg_s[64*256]=16384 | qs[64*64]=4096 | gh[64*257]=16448 | v_s[4*256]=1024 |
//   sred[16*64]=1024   | esh[4*64]=256  | psh[64*4]=256    | bc[16]          |
//   msm[4*256]=1024    | pacc[1024]
#define SM_FLOATS (16384 + 4096 + 16448 + 1024 + 1024 + 256 + 256 + 16 + 1024 + 1024)
#define SM_BYTES  (SM_FLOATS * 4)

__global__ void __launch_bounds__(256, 1) mainK(
    const float* __restrict__ ahs, const float* __restrict__ ghs,
    const float* __restrict__ Wg, const float* __restrict__ bg,
    const float* __restrict__ w,  const float* __restrict__ bias,
    float* __restrict__ out)
{
    extern __shared__ float sm[];
    float* Wg_s = sm;                       // 16384
    float* qs   = Wg_s + DDE * HH;          // 4096   [d][jl]
    float* gh   = qs + DDE * CHUNK;         // 16448  [jl][h] stride 257
    float* v_s  = gh + CHUNK * 257;         // 1024   [z][h]
    float* sred = v_s + NHD * HH;           // 1024   [hq*4+z][jl]
    float* esh  = sred + 1024;              // 256    [z][jl]
    float* psh  = esh + 256;                // 256    [jl][z]
    float* bc   = psh + 256;                // 16
    float* msm  = bc + 16;                  // 1024   [z][h]
    float* pacc = msm + NHD * HH;           // 1024

    const int i   = blockIdx.x;
    const int tid = threadIdx.x;
    const int jl  = tid & 63;
    const int hq  = tid >> 6;

    for (int k = tid; k < DDE * HH; k += 256) Wg_s[k] = Wg[k];
    for (int k = tid; k < NHD * HH; k += 256) v_s[k] = g_v[k];

    // online-softmax state; thread owns h = tid for the m accumulators
    float runmax[NHD], denom[NHD], m[NHD], c1i[NHD];
    const float ahs_i = ahs[i * HH + tid];
    #pragma unroll
    for (int z = 0; z < NHD; z++) {
        c1i[z] = g_c1[z * NN + i];
        const float s = c1i[z] + g_s0[z * NN + i];
        runmax[z] = (s > 0.f) ? s : 0.2f * s;   // leaky-relu of k=0 score
        denom[z]  = 1.f;
        m[z]      = ahs_i;                      // weight exp(e0 - runmax) = 1
    }
    __syncthreads();

    for (int c = 0; c < 4; c++) {
        const int j0 = c * CHUNK;

        // q chunk: q[d][jl] = relu(C[i,d] + PT[d, j0+jl])
        for (int idx = tid; idx < DDE * CHUNK; idx += 256) {
            const int d = idx >> 6, jj = idx & 63;
            const float val = g_C[i * DDE + d] + g_PT[d * NN + j0 + jj];
            qs[idx] = (val > 0.f) ? val : 0.f;
        }
        __syncthreads();

        // gate GEMM: thread (jl, hq) covers row j = j0+jl, columns [hq*64, hq*64+64)
        const int j = j0 + jl;
        const bool diag = (j == i);
        float sp0 = 0.f, sp1 = 0.f, sp2 = 0.f, sp3 = 0.f;

        for (int ht = 0; ht < 8; ht++) {
            const int h0 = hq * 64 + ht * 8;
            const float4 bg0 = *(const float4*)&bg[h0];
            const float4 bg1 = *(const float4*)&bg[h0 + 4];
            float a0 = bg0.x, a1 = bg0.y, a2 = bg0.z, a3 = bg0.w;
            float a4 = bg1.x, a5 = bg1.y, a6 = bg1.z, a7 = bg1.w;
            #pragma unroll 8
            for (int d = 0; d < DDE; d++) {
                const float qd = qs[d * CHUNK + jl];
                const float4 w0 = *(const float4*)&Wg_s[d * HH + h0];
                const float4 w1 = *(const float4*)&Wg_s[d * HH + h0 + 4];
                a0 = fmaf(qd, w0.x, a0); a1 = fmaf(qd, w0.y, a1);
                a2 = fmaf(qd, w0.z, a2); a3 = fmaf(qd, w0.w, a3);
                a4 = fmaf(qd, w1.x, a4); a5 = fmaf(qd, w1.y, a5);
                a6 = fmaf(qd, w1.z, a6); a7 = fmaf(qd, w1.w, a7);
            }
            const float accs[8] = {a0, a1, a2, a3, a4, a5, a6, a7};
            #pragma unroll
            for (int e2 = 0; e2 < 8; e2++) {
                const int h = h0 + e2;
                const float x = accs[e2];
                const float gte = __fdividef(1.f, 1.f + __expf(-x));
                float ghv = gte * g_tT[h * NN + j];
                if (diag) ghv = ghs[i * HH + h];      // gated_h diagonal override
                gh[jl * 257 + h] = ghv;
                sp0 = fmaf(ghv, v_s[h],          sp0);
                sp1 = fmaf(ghv, v_s[HH + h],     sp1);
                sp2 = fmaf(ghv, v_s[2 * HH + h], sp2);
                sp3 = fmaf(ghv, v_s[3 * HH + h], sp3);
            }
        }
        sred[(hq * 4 + 0) * 64 + jl] = sp0;
        sred[(hq * 4 + 1) * 64 + jl] = sp1;
        sred[(hq * 4 + 2) * 64 + jl] = sp2;
        sred[(hq * 4 + 3) * 64 + jl] = sp3;
        __syncthreads();

        // scores + leaky relu (threads 0..63, one per jl)
        if (tid < 64) {
            #pragma unroll
            for (int z = 0; z < NHD; z++) {
                const float s = sred[(0 * 4 + z) * 64 + jl] + sred[(1 * 4 + z) * 64 + jl]
                              + sred[(2 * 4 + z) * 64 + jl] + sred[(3 * 4 + z) * 64 + jl];
                const float sc = c1i[z] + s;
                esh[z * 64 + jl] = (sc > 0.f) ? sc : 0.2f * sc;
            }
        }
        __syncthreads();

        // warp z in {0..3}: chunk max + exp weights + partial sum
        {
            const int wz = tid >> 5;
            if (wz < 4) {
                const int lane = tid & 31;
                const float e1 = esh[wz * 64 + lane];
                const float e2 = esh[wz * 64 + 32 + lane];
                float mx = fmaxf(e1, e2);
                #pragma unroll
                for (int o = 16; o; o >>= 1) mx = fmaxf(mx, __shfl_xor_sync(0xffffffffu, mx, o));
                const float nm = fmaxf(runmax[wz], mx);
                const float p1 = __expf(e1 - nm), p2 = __expf(e2 - nm);
                psh[lane * 4 + wz] = p1;
                psh[(lane + 32) * 4 + wz] = p2;
                float ps = p1 + p2;
                #pragma unroll
                for (int o = 16; o; o >>= 1) ps += __shfl_xor_sync(0xffffffffu, ps, o);
                if (lane == 0) { bc[wz] = mx; bc[4 + wz] = ps; }
            }
        }
        __syncthreads();

        // all threads: merge running state, accumulate m[z] for h = tid
        #pragma unroll
        for (int z = 0; z < NHD; z++) {
            const float nm = fmaxf(runmax[z], bc[z]);
            const float scale = __expf(runmax[z] - nm);
            denom[z] = denom[z] * scale + bc[4 + z];
            runmax[z] = nm;
            m[z] *= scale;
        }
        #pragma unroll 4
        for (int jj = 0; jj < CHUNK; jj++) {
            const float ghv = gh[jj * 257 + tid];
            const float4 p4 = *(const float4*)&psh[jj * 4];
            m[0] = fmaf(p4.x, ghv, m[0]);
            m[1] = fmaf(p4.y, ghv, m[1]);
            m[2] = fmaf(p4.z, ghv, m[2]);
            m[3] = fmaf(p4.w, ghv, m[3]);
        }
        __syncthreads();
    }

    // normalize and stash m
    #pragma unroll
    for (int z = 0; z < NHD; z++) msm[z * HH + tid] = m[z] / denom[z];
    __syncthreads();

    // projection: out[i,f] = relu(0.25 * sum_z m[z]·wm[z,:,f]) + bias[f]
    {
        const int z = hq;            // thread group per head
        const int f0 = jl * 4;
        float4 acc = make_float4(0.f, 0.f, 0.f, 0.f);
        const float* wz = w + z * HH * HH;
        #pragma unroll 4
        for (int h = 0; h < HH; h++) {
            const float mv = msm[z * HH + h];
            const float4 wv = *(const float4*)&wz[h * HH + f0];
            acc.x = fmaf(mv, wv.x, acc.x);
            acc.y = fmaf(mv, wv.y, acc.y);
            acc.z = fmaf(mv, wv.z, acc.z);
            acc.w = fmaf(mv, wv.w, acc.w);
        }
        *(float4*)&pacc[tid * 4] = acc;
    }
    __syncthreads();
    if (tid < 64) {
        const int f0 = tid * 4;
        float4 r = make_float4(0.f, 0.f, 0.f, 0.f);
        #pragma unroll
        for (int z = 0; z < NHD; z++) {
            const float4 pz = *(const float4*)&pacc[(z * 64 + tid) * 4];
            r.x += pz.x; r.y += pz.y; r.z += pz.z; r.w += pz.w;
        }
        const float4 bv = *(const float4*)&bias[f0];
        r.x = fmaxf(0.25f * r.x, 0.f) + bv.x;
        r.y = fmaxf(0.25f * r.y, 0.f) + bv.y;
        r.z = fmaxf(0.25f * r.z, 0.f) + bv.z;
        r.w = fmaxf(0.25f * r.w, 0.f) + bv.w;
        *(float4*)&out[i * HH + f0] = r;
    }
}

// ---------------- launch ----------------
extern "C" void kernel_launch(void* const* d_in, const int* in_sizes, int n_in,
                              void* d_out, int out_size) {
    (void)in_sizes; (void)n_in; (void)out_size;
    const float* ahs    = (const float*)d_in[0];
    const float* ghs    = (const float*)d_in[1];
    const float* goal   = (const float*)d_in[2];
    const float* action = (const float*)d_in[3];
    const float* Wd     = (const float*)d_in[4];
    const float* bd     = (const float*)d_in[5];
    const float* Wg     = (const float*)d_in[6];
    const float* bg     = (const float*)d_in[7];
    const float* w      = (const float*)d_in[8];
    const float* a      = (const float*)d_in[9];
    const float* bias   = (const float*)d_in[10];
    float* out = (float*)d_out;

    cudaFuncSetAttribute(mainK, cudaFuncAttributeMaxDynamicSharedMemorySize, SM_BYTES);

    prepA<<<NN, 256>>>(ahs, goal, action, Wd, bd);
    prepB<<<128, 256>>>(w, a);
    prepC<<<128, 256>>>(ahs);
    mainK<<<NN, 256, SM_BYTES>>>(ahs, ghs, Wg, bg, w, bias, out);
}

// round 2
// speedup vs baseline: 1.3647x; 1.3647x over previous
#include <cuda_runtime.h>
#include <math.h>

#define NN 256
#define HH 256
#define DDE 64
#define NHD 4
#define CHUNK 64
#define GH_STRIDE 260

// ---------------- device scratch (static, no allocations) ----------------
__device__ float g_tTj[NN * HH];   // tTj[j*H + h] = tanh(ahs[j,h])
__device__ float g_PT[DDE * NN];   // PT[d*N + j]
__device__ float g_C [NN * DDE];   // C[i*DDE + d]
__device__ float g_u [NHD * HH];
__device__ float g_v [NHD * HH];
__device__ float g_c1[NHD * NN];   // c1[z*N+n] = ahs[n]·u[z]
__device__ float g_s0[NHD * NN];   // s0[z*N+n] = ahs[n]·v[z]
__device__ float g_msm[NN * NHD * HH];  // msm[n*1024 + z*256 + h]

// ---------------- prep kernels ----------------
__global__ void prepA(const float* __restrict__ ahs, const float* __restrict__ goal,
                      const float* __restrict__ action, const float* __restrict__ Wd,
                      const float* __restrict__ bd) {
    const int j = blockIdx.x, t = threadIdx.x;
    g_tTj[j * HH + t] = tanhf(ahs[j * HH + t]);
    if (t < DDE) {
        const float a0 = action[j * 2 + 0], a1 = action[j * 2 + 1];
        const float go0 = goal[j * 2 + 0], go1 = goal[j * 2 + 1];
        g_PT[t * NN + j] = a0 * Wd[4 * DDE + t] + a1 * Wd[5 * DDE + t]
                         + go0 * Wd[6 * DDE + t] + go1 * Wd[7 * DDE + t];
        g_C[j * DDE + t] = a0 * Wd[0 * DDE + t] + a1 * Wd[1 * DDE + t]
                         + go0 * Wd[2 * DDE + t] + go1 * Wd[3 * DDE + t] + bd[t];
    }
}

__global__ void prepB(const float* __restrict__ w, const float* __restrict__ a) {
    const int warp = (blockIdx.x * blockDim.x + threadIdx.x) >> 5;  // z*256+h
    const int lane = threadIdx.x & 31;
    const float* row = w + warp * HH;
    float su = 0.f, sv = 0.f;
    #pragma unroll
    for (int f = lane; f < HH; f += 32) {
        const float wv = row[f];
        su = fmaf(wv, a[f], su);
        sv = fmaf(wv, a[HH + f], sv);
    }
    #pragma unroll
    for (int o = 16; o; o >>= 1) {
        su += __shfl_down_sync(0xffffffffu, su, o);
        sv += __shfl_down_sync(0xffffffffu, sv, o);
    }
    if (lane == 0) { g_u[warp] = su; g_v[warp] = sv; }
}

__global__ void prepC(const float* __restrict__ ahs) {
    const int warp = (blockIdx.x * blockDim.x + threadIdx.x) >> 5;  // z*256+n
    const int lane = threadIdx.x & 31;
    const int z = warp >> 8, n = warp & 255;
    float sc = 0.f, ss = 0.f;
    #pragma unroll
    for (int h = lane; h < HH; h += 32) {
        const float av = ahs[n * HH + h];
        sc = fmaf(av, g_u[z * HH + h], sc);
        ss = fmaf(av, g_v[z * HH + h], ss);
    }
    #pragma unroll
    for (int o = 16; o; o >>= 1) {
        sc += __shfl_down_sync(0xffffffffu, sc, o);
        ss += __shfl_down_sync(0xffffffffu, ss, o);
    }
    if (lane == 0) { g_c1[warp] = sc; g_s0[warp] = ss; }
}

// ---------------- main fused kernel: one block per row i ----------------
// shared floats: Wg_s 16384 | qs 4096 | gh 64*260=16640 | v_s 1024 | esh 256 | psh 256 | bc 16
#define SM_FLOATS (16384 + 4096 + 64 * GH_STRIDE + 1024 + 256 + 256 + 16)
#define SM_BYTES  (SM_FLOATS * 4)

__global__ void __launch_bounds__(256, 1) mainK(
    const float* __restrict__ ahs, const float* __restrict__ ghs,
    const float* __restrict__ Wg, const float* __restrict__ bg)
{
    extern __shared__ float sm[];
    float* Wg_s = sm;                       // [d][h]  16384
    float* qs   = Wg_s + DDE * HH;          // [d][j]  4096
    float* gh   = qs + DDE * CHUNK;         // [j][h]  stride 260
    float* v_s  = gh + CHUNK * GH_STRIDE;   // [z][h]  1024
    float* esh  = v_s + NHD * HH;           // [z][jl] 256
    float* psh  = esh + 256;                // [jl][z] 256
    float* bc   = psh + 256;                // 16

    const int i    = blockIdx.x;
    const int tid  = threadIdx.x;
    const int th   = tid & 31;              // h-group for GEMM
    const int tj   = tid >> 5;              // j-group (warp) for GEMM
    const int lane = tid & 31;

    for (int k = tid; k < DDE * HH; k += 256) Wg_s[k] = Wg[k];
    for (int k = tid; k < NHD * HH; k += 256) v_s[k] = g_v[k];

    // bias of gate (constant across chunks) — thread's 8 h = {th*4+0..3, 128+th*4+0..3}
    const float4 bg0 = *(const float4*)&bg[th * 4];
    const float4 bg1 = *(const float4*)&bg[128 + th * 4];

    // online-softmax state (identical across threads for runmax/denom)
    float runmax[NHD], denom[NHD], m[NHD];
    const float ahs_i = ahs[i * HH + tid];
    #pragma unroll
    for (int z = 0; z < NHD; z++) {
        const float s = g_c1[z * NN + i] + g_s0[z * NN + i];
        runmax[z] = (s > 0.f) ? s : 0.2f * s;   // leaky relu of k=0 score
        denom[z]  = 1.f;
        m[z]      = ahs_i;
    }
    const float cz = g_c1[(lane & 3) * NN + i];   // for sp-pass lanes 0..3
    __syncthreads();

    for (int c = 0; c < 4; c++) {
        const int j0 = c * CHUNK;

        // q chunk: qs[d][jj] = relu(C[i,d] + PT[d, j0+jj])
        for (int idx = tid; idx < DDE * CHUNK; idx += 256) {
            const int d = idx >> 6, jj = idx & 63;
            const float val = g_C[i * DDE + d] + g_PT[d * NN + j0 + jj];
            qs[idx] = (val > 0.f) ? val : 0.f;
        }
        __syncthreads();

        // ---- register-blocked gate GEMM: 8 j x 8 h per thread ----
        float acc[8][8];
        #pragma unroll
        for (int jj = 0; jj < 8; jj++) {
            acc[jj][0] = bg0.x; acc[jj][1] = bg0.y; acc[jj][2] = bg0.z; acc[jj][3] = bg0.w;
            acc[jj][4] = bg1.x; acc[jj][5] = bg1.y; acc[jj][6] = bg1.z; acc[jj][7] = bg1.w;
        }
        #pragma unroll 4
        for (int d = 0; d < DDE; d++) {
            const float4 qa = *(const float4*)&qs[d * CHUNK + tj * 8];
            const float4 qb = *(const float4*)&qs[d * CHUNK + tj * 8 + 4];
            const float4 wa = *(const float4*)&Wg_s[d * HH + th * 4];
            const float4 wb = *(const float4*)&Wg_s[d * HH + 128 + th * 4];
            const float q8[8] = {qa.x, qa.y, qa.z, qa.w, qb.x, qb.y, qb.z, qb.w};
            const float w8[8] = {wa.x, wa.y, wa.z, wa.w, wb.x, wb.y, wb.z, wb.w};
            #pragma unroll
            for (int jj = 0; jj < 8; jj++)
                #pragma unroll
                for (int hh = 0; hh < 8; hh++)
                    acc[jj][hh] = fmaf(q8[jj], w8[hh], acc[jj][hh]);
        }

        // ---- epilogue: sigmoid * tanh (diag override), store gh ----
        #pragma unroll
        for (int jj = 0; jj < 8; jj++) {
            const int jloc = tj * 8 + jj;
            const int j = j0 + jloc;
            float gv[8];
            if (j == i) {
                const float4 ga = *(const float4*)&ghs[i * HH + th * 4];
                const float4 gb = *(const float4*)&ghs[i * HH + 128 + th * 4];
                gv[0] = ga.x; gv[1] = ga.y; gv[2] = ga.z; gv[3] = ga.w;
                gv[4] = gb.x; gv[5] = gb.y; gv[6] = gb.z; gv[7] = gb.w;
            } else {
                const float4 ta = *(const float4*)&g_tTj[j * HH + th * 4];
                const float4 tb = *(const float4*)&g_tTj[j * HH + 128 + th * 4];
                const float t8[8] = {ta.x, ta.y, ta.z, ta.w, tb.x, tb.y, tb.z, tb.w};
                #pragma unroll
                for (int hh = 0; hh < 8; hh++) {
                    const float x = acc[jj][hh];
                    const float sg = __fdividef(1.f, 1.f + __expf(-x));
                    gv[hh] = sg * t8[hh];
                }
            }
            *(float4*)&gh[jloc * GH_STRIDE + th * 4]       = make_float4(gv[0], gv[1], gv[2], gv[3]);
            *(float4*)&gh[jloc * GH_STRIDE + 128 + th * 4] = make_float4(gv[4], gv[5], gv[6], gv[7]);
        }
        __syncthreads();

        // ---- score pass: warp tj handles rows [tj*8, tj*8+8), lanes split h ----
        {
            const float4 v0a = *(const float4*)&v_s[0 * HH + lane * 4];
            const float4 v0b = *(const float4*)&v_s[0 * HH + 128 + lane * 4];
            const float4 v1a = *(const float4*)&v_s[1 * HH + lane * 4];
            const float4 v1b = *(const float4*)&v_s[1 * HH + 128 + lane * 4];
            const float4 v2a = *(const float4*)&v_s[2 * HH + lane * 4];
            const float4 v2b = *(const float4*)&v_s[2 * HH + 128 + lane * 4];
            const float4 v3a = *(const float4*)&v_s[3 * HH + lane * 4];
            const float4 v3b = *(const float4*)&v_s[3 * HH + 128 + lane * 4];
            #pragma unroll
            for (int r = 0; r < 8; r++) {
                const int jl = tj * 8 + r;
                const float4 ga = *(const float4*)&gh[jl * GH_STRIDE + lane * 4];
                const float4 gb = *(const float4*)&gh[jl * GH_STRIDE + 128 + lane * 4];
                float p0, p1, p2, p3;
                p0 = ga.x*v0a.x + ga.y*v0a.y + ga.z*v0a.z + ga.w*v0a.w
                   + gb.x*v0b.x + gb.y*v0b.y + gb.z*v0b.z + gb.w*v0b.w;
                p1 = ga.x*v1a.x + ga.y*v1a.y + ga.z*v1a.z + ga.w*v1a.w
                   + gb.x*v1b.x + gb.y*v1b.y + gb.z*v1b.z + gb.w*v1b.w;
                p2 = ga.x*v2a.x + ga.y*v2a.y + ga.z*v2a.z + ga.w*v2a.w
                   + gb.x*v2b.x + gb.y*v2b.y + gb.z*v2b.z + gb.w*v2b.w;
                p3 = ga.x*v3a.x + ga.y*v3a.y + ga.z*v3a.z + ga.w*v3a.w
                   + gb.x*v3b.x + gb.y*v3b.y + gb.z*v3b.z + gb.w*v3b.w;
                #pragma unroll
                for (int o = 16; o; o >>= 1) {
                    p0 += __shfl_xor_sync(0xffffffffu, p0, o);
                    p1 += __shfl_xor_sync(0xffffffffu, p1, o);
                    p2 += __shfl_xor_sync(0xffffffffu, p2, o);
                    p3 += __shfl_xor_sync(0xffffffffu, p3, o);
                }
                if (lane < 4) {
                    const float sv = (lane == 0) ? p0 : (lane == 1) ? p1 : (lane == 2) ? p2 : p3;
                    const float sc = cz + sv;
                    esh[lane * 64 + jl] = (sc > 0.f) ? sc : 0.2f * sc;
                }
            }
        }
        __syncthreads();

        // ---- chunk softmax: warp z computes max + exp weights + partial sum ----
        {
            const int wz = tid >> 5;
            if (wz < 4) {
                const float e1 = esh[wz * 64 + lane];
                const float e2 = esh[wz * 64 + 32 + lane];
                float mx = fmaxf(e1, e2);
                #pragma unroll
                for (int o = 16; o; o >>= 1) mx = fmaxf(mx, __shfl_xor_sync(0xffffffffu, mx, o));
                const float nm = fmaxf(runmax[wz], mx);
                const float p1 = __expf(e1 - nm), p2 = __expf(e2 - nm);
                psh[lane * 4 + wz] = p1;
                psh[(lane + 32) * 4 + wz] = p2;
                float ps = p1 + p2;
                #pragma unroll
                for (int o = 16; o; o >>= 1) ps += __shfl_xor_sync(0xffffffffu, ps, o);
                if (lane == 0) { bc[wz] = mx; bc[4 + wz] = ps; }
            }
        }
        __syncthreads();

        // ---- merge running state, accumulate m[z] for h = tid ----
        #pragma unroll
        for (int z = 0; z < NHD; z++) {
            const float nm = fmaxf(runmax[z], bc[z]);
            const float scale = __expf(runmax[z] - nm);
            denom[z] = denom[z] * scale + bc[4 + z];
            runmax[z] = nm;
            m[z] *= scale;
        }
        #pragma unroll 4
        for (int jj = 0; jj < CHUNK; jj++) {
            const float ghv = gh[jj * GH_STRIDE + tid];
            const float4 p4 = *(const float4*)&psh[jj * 4];
            m[0] = fmaf(p4.x, ghv, m[0]);
            m[1] = fmaf(p4.y, ghv, m[1]);
            m[2] = fmaf(p4.z, ghv, m[2]);
            m[3] = fmaf(p4.w, ghv, m[3]);
        }
        __syncthreads();
    }

    // write normalized m to global scratch: g_msm[i][z*256 + h]
    #pragma unroll
    for (int z = 0; z < NHD; z++)
        g_msm[i * (NHD * HH) + z * HH + tid] = m[z] / denom[z];
}

// ---------------- projection kernel ----------------
// out[n,f] = relu(0.25 * sum_k msm[n,k] * w[k,f]) + bias[f],  k = z*256+h (1024)
// grid 256: 32 n-tiles (8 rows) x 8 f-tiles (32 cols). 256 threads: fl=f, kw=k-slice.
__global__ void __launch_bounds__(256) projK(const float* __restrict__ w,
                                             const float* __restrict__ bias,
                                             float* __restrict__ out) {
    __shared__ float msm_s[8192];   // [k][n], n contiguous (8)
    __shared__ float sacc[2048];    // [kw][n][fl]
    const int tid = threadIdx.x;
    const int f0 = (blockIdx.x & 7) * 32;
    const int n0 = (blockIdx.x >> 3) * 8;

    for (int idx = tid; idx < 8192; idx += 256) {
        const int k = idx >> 3, n = idx & 7;
        msm_s[idx] = g_msm[(n0 + n) * 1024 + k];
    }
    __syncthreads();

    const int fl = tid & 31, kw = tid >> 5;
    float acc[8] = {0.f, 0.f, 0.f, 0.f, 0.f, 0.f, 0.f, 0.f};
    const float* wp = w + f0 + fl;
    const int kbeg = kw * 128;
    #pragma unroll 4
    for (int k = kbeg; k < kbeg + 128; k++) {
        const float wv = wp[k * 256];
        const float4 ma = *(const float4*)&msm_s[k * 8];
        const float4 mb = *(const float4*)&msm_s[k * 8 + 4];
        acc[0] = fmaf(wv, ma.x, acc[0]); acc[1] = fmaf(wv, ma.y, acc[1]);
        acc[2] = fmaf(wv, ma.z, acc[2]); acc[3] = fmaf(wv, ma.w, acc[3]);
        acc[4] = fmaf(wv, mb.x, acc[4]); acc[5] = fmaf(wv, mb.y, acc[5]);
        acc[6] = fmaf(wv, mb.z, acc[6]); acc[7] = fmaf(wv, mb.w, acc[7]);
    }
    #pragma unroll
    for (int n = 0; n < 8; n++) sacc[(kw * 8 + n) * 32 + fl] = acc[n];
    __syncthreads();

    const int n = tid >> 5;
    float s = 0.f;
    #pragma unroll
    for (int k2 = 0; k2 < 8; k2++) s += sacc[(k2 * 8 + n) * 32 + fl];
    out[(n0 + n) * 256 + f0 + fl] = fmaxf(0.25f * s, 0.f) + bias[f0 + fl];
}

// ---------------- launch ----------------
extern "C" void kernel_launch(void* const* d_in, const int* in_sizes, int n_in,
                              void* d_out, int out_size) {
    (void)in_sizes; (void)n_in; (void)out_size;
    const float* ahs    = (const float*)d_in[0];
    const float* ghs    = (const float*)d_in[1];
    const float* goal   = (const float*)d_in[2];
    const float* action = (const float*)d_in[3];
    const float* Wd     = (const float*)d_in[4];
    const float* bd     = (const float*)d_in[5];
    const float* Wg     = (const float*)d_in[6];
    const float* bg     = (const float*)d_in[7];
    const float* w      = (const float*)d_in[8];
    const float* a      = (const float*)d_in[9];
    const float* bias   = (const float*)d_in[10];
    float* out = (float*)d_out;

    cudaFuncSetAttribute(mainK, cudaFuncAttributeMaxDynamicSharedMemorySize, SM_BYTES);

    prepA<<<NN, 256>>>(ahs, goal, action, Wd, bd);
    prepB<<<128, 256>>>(w, a);
    prepC<<<128, 256>>>(ahs);
    mainK<<<NN, 256, SM_BYTES>>>(ahs, ghs, Wg, bg);
    projK<<<NN, 256>>>(w, bias, out);
}

// round 3
// speedup vs baseline: 1.6390x; 1.2010x over previous
#include <cuda_runtime.h>
#include <math.h>

#define NN 256
#define HH 256
#define DDE 64
#define NHD 4
#define CHUNK 32
#define NCHUNK 8
#define GH_STRIDE 260

// ---------------- device scratch (static, no allocations) ----------------
__device__ float g_tTj[NN * HH];   // tTj[j*H + h] = tanh(ahs[j,h])
__device__ float g_PT[DDE * NN];   // PT[d*N + j]
__device__ float g_C [NN * DDE];   // C[i*DDE + d]
__device__ float g_u [NHD * HH];
__device__ float g_v [NHD * HH];
__device__ float g_c1[NHD * NN];   // c1[z*N+n] = ahs[n]·u[z]
__device__ float g_s0[NHD * NN];   // s0[z*N+n] = ahs[n]·v[z]
__device__ float g_msm[NN * NHD * HH];  // msm[n*1024 + z*256 + h]

// ---------------- prep kernels ----------------
__global__ void prepA(const float* __restrict__ ahs, const float* __restrict__ goal,
                      const float* __restrict__ action, const float* __restrict__ Wd,
                      const float* __restrict__ bd) {
    const int j = blockIdx.x, t = threadIdx.x;
    g_tTj[j * HH + t] = tanhf(ahs[j * HH + t]);
    if (t < DDE) {
        const float a0 = action[j * 2 + 0], a1 = action[j * 2 + 1];
        const float go0 = goal[j * 2 + 0], go1 = goal[j * 2 + 1];
        g_PT[t * NN + j] = a0 * Wd[4 * DDE + t] + a1 * Wd[5 * DDE + t]
                         + go0 * Wd[6 * DDE + t] + go1 * Wd[7 * DDE + t];
        g_C[j * DDE + t] = a0 * Wd[0 * DDE + t] + a1 * Wd[1 * DDE + t]
                         + go0 * Wd[2 * DDE + t] + go1 * Wd[3 * DDE + t] + bd[t];
    }
}

__global__ void prepB(const float* __restrict__ w, const float* __restrict__ a) {
    const int warp = (blockIdx.x * blockDim.x + threadIdx.x) >> 5;  // z*256+h
    const int lane = threadIdx.x & 31;
    const float* row = w + warp * HH;
    float su = 0.f, sv = 0.f;
    #pragma unroll
    for (int f = lane; f < HH; f += 32) {
        const float wv = row[f];
        su = fmaf(wv, a[f], su);
        sv = fmaf(wv, a[HH + f], sv);
    }
    #pragma unroll
    for (int o = 16; o; o >>= 1) {
        su += __shfl_down_sync(0xffffffffu, su, o);
        sv += __shfl_down_sync(0xffffffffu, sv, o);
    }
    if (lane == 0) { g_u[warp] = su; g_v[warp] = sv; }
}

__global__ void prepC(const float* __restrict__ ahs) {
    const int warp = (blockIdx.x * blockDim.x + threadIdx.x) >> 5;  // z*256+n
    const int lane = threadIdx.x & 31;
    const int z = warp >> 8, n = warp & 255;
    float sc = 0.f, ss = 0.f;
    #pragma unroll
    for (int h = lane; h < HH; h += 32) {
        const float av = ahs[n * HH + h];
        sc = fmaf(av, g_u[z * HH + h], sc);
        ss = fmaf(av, g_v[z * HH + h], ss);
    }
    #pragma unroll
    for (int o = 16; o; o >>= 1) {
        sc += __shfl_down_sync(0xffffffffu, sc, o);
        ss += __shfl_down_sync(0xffffffffu, ss, o);
    }
    if (lane == 0) { g_c1[warp] = sc; g_s0[warp] = ss; }
}

// ---------------- main fused kernel: one block per row i, 2 CTAs/SM ----------------
// shared floats: Wg_s 16384 | qs 64*32=2048 | gh 32*260=8320 | esh 128 | psh 128 | bc 16
#define SM_FLOATS (16384 + 2048 + CHUNK * GH_STRIDE + 128 + 128 + 16)
#define SM_BYTES  (SM_FLOATS * 4)

__global__ void __launch_bounds__(256, 2) mainK(
    const float* __restrict__ ahs, const float* __restrict__ ghs,
    const float* __restrict__ Wg, const float* __restrict__ bg)
{
    extern __shared__ float sm[];
    float* Wg_s = sm;                       // [d][h]   16384
    float* qs   = Wg_s + DDE * HH;          // [d][jl]  2048
    float* gh   = qs + DDE * CHUNK;         // [jl][h]  stride 260
    float* esh  = gh + CHUNK * GH_STRIDE;   // [z][jl]  128
    float* psh  = esh + 128;                // [jl][z]  128
    float* bc   = psh + 128;                // 16

    const int i    = blockIdx.x;
    const int tid  = threadIdx.x;
    const int th   = tid & 31;              // lane: h-group
    const int tj   = tid >> 5;              // warp: j-group
    const int lane = th;

    for (int k = tid; k < DDE * HH; k += 256) Wg_s[k] = Wg[k];

    // preload per-thread v values (h = th*4+e and 128+th*4+e) for all 4 heads
    float vz[NHD][8];
    #pragma unroll
    for (int z = 0; z < NHD; z++) {
        const float4 va = *(const float4*)&g_v[z * HH + th * 4];
        const float4 vb = *(const float4*)&g_v[z * HH + 128 + th * 4];
        vz[z][0] = va.x; vz[z][1] = va.y; vz[z][2] = va.z; vz[z][3] = va.w;
        vz[z][4] = vb.x; vz[z][5] = vb.y; vz[z][6] = vb.z; vz[z][7] = vb.w;
    }
    const float4 bg0 = *(const float4*)&bg[th * 4];
    const float4 bg1 = *(const float4*)&bg[128 + th * 4];

    // online-softmax state (runmax/denom replicated across threads)
    float runmax[NHD], denom[NHD], m[NHD];
    const float ahs_i = ahs[i * HH + tid];
    #pragma unroll
    for (int z = 0; z < NHD; z++) {
        const float s = g_c1[z * NN + i] + g_s0[z * NN + i];
        runmax[z] = (s > 0.f) ? s : 0.2f * s;   // leaky relu of k=0 score
        denom[z]  = 1.f;
        m[z]      = ahs_i;
    }
    const float cz = g_c1[(lane & 3) * NN + i];
    __syncthreads();

    for (int c = 0; c < NCHUNK; c++) {
        const int j0 = c * CHUNK;

        // qs[d][jj] = relu(C[i,d] + PT[d, j0+jj])
        for (int idx = tid; idx < DDE * CHUNK; idx += 256) {
            const int d = idx >> 5, jj = idx & 31;
            const float val = g_C[i * DDE + d] + g_PT[d * NN + j0 + jj];
            qs[idx] = fmaxf(val, 0.f);
        }
        __syncthreads();

        // ---- register-blocked gate GEMM: 4 j x 8 h per thread ----
        float acc[4][8];
        #pragma unroll
        for (int jj = 0; jj < 4; jj++) {
            acc[jj][0] = bg0.x; acc[jj][1] = bg0.y; acc[jj][2] = bg0.z; acc[jj][3] = bg0.w;
            acc[jj][4] = bg1.x; acc[jj][5] = bg1.y; acc[jj][6] = bg1.z; acc[jj][7] = bg1.w;
        }
        #pragma unroll 4
        for (int d = 0; d < DDE; d++) {
            const float4 q4 = *(const float4*)&qs[d * CHUNK + tj * 4];
            const float4 wa = *(const float4*)&Wg_s[d * HH + th * 4];
            const float4 wb = *(const float4*)&Wg_s[d * HH + 128 + th * 4];
            const float q_[4] = {q4.x, q4.y, q4.z, q4.w};
            const float w8[8] = {wa.x, wa.y, wa.z, wa.w, wb.x, wb.y, wb.z, wb.w};
            #pragma unroll
            for (int jj = 0; jj < 4; jj++)
                #pragma unroll
                for (int hh = 0; hh < 8; hh++)
                    acc[jj][hh] = fmaf(q_[jj], w8[hh], acc[jj][hh]);
        }

        // ---- epilogue: sigmoid*tanh (diag override), store gh, fused scores ----
        #pragma unroll
        for (int jj = 0; jj < 4; jj++) {
            const int jloc = tj * 4 + jj;
            const int j = j0 + jloc;
            float gv[8];
            if (j == i) {
                const float4 ga = *(const float4*)&ghs[i * HH + th * 4];
                const float4 gb = *(const float4*)&ghs[i * HH + 128 + th * 4];
                gv[0] = ga.x; gv[1] = ga.y; gv[2] = ga.z; gv[3] = ga.w;
                gv[4] = gb.x; gv[5] = gb.y; gv[6] = gb.z; gv[7] = gb.w;
            } else {
                const float4 ta = *(const float4*)&g_tTj[j * HH + th * 4];
                const float4 tb = *(const float4*)&g_tTj[j * HH + 128 + th * 4];
                const float t8[8] = {ta.x, ta.y, ta.z, ta.w, tb.x, tb.y, tb.z, tb.w};
                #pragma unroll
                for (int hh = 0; hh < 8; hh++) {
                    const float x = acc[jj][hh];
                    const float sg = __fdividef(1.f, 1.f + __expf(-x));
                    gv[hh] = sg * t8[hh];
                }
            }
            *(float4*)&gh[jloc * GH_STRIDE + th * 4]       = make_float4(gv[0], gv[1], gv[2], gv[3]);
            *(float4*)&gh[jloc * GH_STRIDE + 128 + th * 4] = make_float4(gv[4], gv[5], gv[6], gv[7]);

            // fused score partials from registers
            float p0 = 0.f, p1 = 0.f, p2 = 0.f, p3 = 0.f;
            #pragma unroll
            for (int hh = 0; hh < 8; hh++) {
                p0 = fmaf(gv[hh], vz[0][hh], p0);
                p1 = fmaf(gv[hh], vz[1][hh], p1);
                p2 = fmaf(gv[hh], vz[2][hh], p2);
                p3 = fmaf(gv[hh], vz[3][hh], p3);
            }
            #pragma unroll
            for (int o = 16; o; o >>= 1) {
                p0 += __shfl_xor_sync(0xffffffffu, p0, o);
                p1 += __shfl_xor_sync(0xffffffffu, p1, o);
                p2 += __shfl_xor_sync(0xffffffffu, p2, o);
                p3 += __shfl_xor_sync(0xffffffffu, p3, o);
            }
            if (lane < 4) {
                const float sv = (lane == 0) ? p0 : (lane == 1) ? p1 : (lane == 2) ? p2 : p3;
                const float sc = cz + sv;
                esh[lane * CHUNK + jloc] = (sc > 0.f) ? sc : 0.2f * sc;
            }
        }
        __syncthreads();

        // ---- chunk softmax: warp z in {0..3} ----
        if (tj < 4) {
            const float e = esh[tj * CHUNK + lane];
            float mx = e;
            #pragma unroll
            for (int o = 16; o; o >>= 1) mx = fmaxf(mx, __shfl_xor_sync(0xffffffffu, mx, o));
            const float nm = fmaxf(runmax[tj], mx);
            const float p = __expf(e - nm);
            psh[lane * 4 + tj] = p;
            float ps = p;
            #pragma unroll
            for (int o = 16; o; o >>= 1) ps += __shfl_xor_sync(0xffffffffu, ps, o);
            if (lane == 0) { bc[tj] = mx; bc[4 + tj] = ps; }
        }
        __syncthreads();

        // ---- merge running state, accumulate m[z] for h = tid ----
        #pragma unroll
        for (int z = 0; z < NHD; z++) {
            const float nm = fmaxf(runmax[z], bc[z]);
            const float scale = __expf(runmax[z] - nm);
            denom[z] = denom[z] * scale + bc[4 + z];
            runmax[z] = nm;
            m[z] *= scale;
        }
        #pragma unroll 4
        for (int jj = 0; jj < CHUNK; jj++) {
            const float ghv = gh[jj * GH_STRIDE + tid];
            const float4 p4 = *(const float4*)&psh[jj * 4];
            m[0] = fmaf(p4.x, ghv, m[0]);
            m[1] = fmaf(p4.y, ghv, m[1]);
            m[2] = fmaf(p4.z, ghv, m[2]);
            m[3] = fmaf(p4.w, ghv, m[3]);
        }
        __syncthreads();
    }

    // write normalized m: g_msm[i][z*256 + h]
    #pragma unroll
    for (int z = 0; z < NHD; z++)
        g_msm[i * (NHD * HH) + z * HH + tid] = m[z] / denom[z];
}

// ---------------- projection kernel ----------------
__global__ void __launch_bounds__(256) projK(const float* __restrict__ w,
                                             const float* __restrict__ bias,
                                             float* __restrict__ out) {
    __shared__ float msm_s[8192];   // [k][n], n contiguous (8)
    __shared__ float sacc[2048];    // [kw][n][fl]
    const int tid = threadIdx.x;
    const int f0 = (blockIdx.x & 7) * 32;
    const int n0 = (blockIdx.x >> 3) * 8;

    for (int idx = tid; idx < 8192; idx += 256) {
        const int k = idx >> 3, n = idx & 7;
        msm_s[idx] = g_msm[(n0 + n) * 1024 + k];
    }
    __syncthreads();

    const int fl = tid & 31, kw = tid >> 5;
    float acc[8] = {0.f, 0.f, 0.f, 0.f, 0.f, 0.f, 0.f, 0.f};
    const float* wp = w + f0 + fl;
    const int kbeg = kw * 128;
    #pragma unroll 4
    for (int k = kbeg; k < kbeg + 128; k++) {
        const float wv = wp[k * 256];
        const float4 ma = *(const float4*)&msm_s[k * 8];
        const float4 mb = *(const float4*)&msm_s[k * 8 + 4];
        acc[0] = fmaf(wv, ma.x, acc[0]); acc[1] = fmaf(wv, ma.y, acc[1]);
        acc[2] = fmaf(wv, ma.z, acc[2]); acc[3] = fmaf(wv, ma.w, acc[3]);
        acc[4] = fmaf(wv, mb.x, acc[4]); acc[5] = fmaf(wv, mb.y, acc[5]);
        acc[6] = fmaf(wv, mb.z, acc[6]); acc[7] = fmaf(wv, mb.w, acc[7]);
    }
    #pragma unroll
    for (int n = 0; n < 8; n++) sacc[(kw * 8 + n) * 32 + fl] = acc[n];
    __syncthreads();

    const int n = tid >> 5;
    float s = 0.f;
    #pragma unroll
    for (int k2 = 0; k2 < 8; k2++) s += sacc[(k2 * 8 + n) * 32 + fl];
    out[(n0 + n) * 256 + f0 + fl] = fmaxf(0.25f * s, 0.f) + bias[f0 + fl];
}

// ---------------- launch ----------------
extern "C" void kernel_launch(void* const* d_in, const int* in_sizes, int n_in,
                              void* d_out, int out_size) {
    (void)in_sizes; (void)n_in; (void)out_size;
    const float* ahs    = (const float*)d_in[0];
    const float* ghs    = (const float*)d_in[1];
    const float* goal   = (const float*)d_in[2];
    const float* action = (const float*)d_in[3];
    const float* Wd     = (const float*)d_in[4];
    const float* bd     = (const float*)d_in[5];
    const float* Wg     = (const float*)d_in[6];
    const float* bg     = (const float*)d_in[7];
    const float* w      = (const float*)d_in[8];
    const float* a      = (const float*)d_in[9];
    const float* bias   = (const float*)d_in[10];
    float* out = (float*)d_out;

    cudaFuncSetAttribute(mainK, cudaFuncAttributeMaxDynamicSharedMemorySize, SM_BYTES);

    prepA<<<NN, 256>>>(ahs, goal, action, Wd, bd);
    prepB<<<128, 256>>>(w, a);
    prepC<<<128, 256>>>(ahs);
    mainK<<<NN, 256, SM_BYTES>>>(ahs, ghs, Wg, bg);
    projK<<<NN, 256>>>(w, bias, out);
}